// round 15
// baseline (speedup 1.0000x reference)
#include <cuda_runtime.h>
#include <cstdint>

// KNRM: mma.sync bf16 3-split, cp.async raw staging -> smem convert -> ldsm/MMA.
// B=128, Q=16, D=1024, E=300, K=11. Grid 128, 256 threads, 1 CTA/SM.
#define B_SZ 128
#define Q_SZ 16
#define D_SZ 1024
#define E_SZ 300
#define K_SZ 11
#define NT 256
#define MT 64                    // doc rows per tile
#define NTILE 16
#define NKS 19                   // k-steps of 16 (covers 304 >= 300)
#define RSTR_B 1312              // raw fp32 row stride bytes (328 floats)
#define STRB 624                 // bf16 row stride bytes (312 cols)

#define OFF_RAW  0                           // 64 x 1312 = 83968
#define OFF_AHI  83968                       // 64 x 624
#define OFF_ALO  123904                      // 64 x 624
#define OFF_BHI  163840                      // 16 x 624
#define OFF_BLO  173824                      // 16 x 624
#define OFF_RND  183808                      // 64 floats
#define OFF_RNQ  184064                      // 16 floats
#define OFF_RED  184128                      // 8 warps x 4 m x 24 floats
#define OFF_QFIN 187200                      // 192 floats
#define SMEM_BYTES 187984

__device__ __forceinline__ uint32_t smem_u32(const void* p) {
    uint32_t a;
    asm("{ .reg .u64 t; cvta.to.shared.u64 t, %1; cvt.u32.u64 %0, t; }" : "=r"(a) : "l"(p));
    return a;
}
__device__ __forceinline__ float ex2f(float x) {
    float y; asm("ex2.approx.f32 %0, %1;" : "=f"(y) : "f"(x)); return y;
}
__device__ __forceinline__ uint32_t packbf(float lo, float hi) {
    uint32_t r;
    asm("cvt.rn.bf16x2.f32 %0, %1, %2;" : "=r"(r) : "f"(hi), "f"(lo));
    return r;
}
__device__ __forceinline__ void sts64(uint32_t a, uint32_t x, uint32_t y) {
    asm volatile("st.shared.v2.b32 [%0], {%1, %2};" :: "r"(a), "r"(x), "r"(y) : "memory");
}
__device__ __forceinline__ float4 lds128(uint32_t a) {
    float4 v;
    asm volatile("ld.shared.v4.f32 {%0,%1,%2,%3}, [%4];"
                 : "=f"(v.x), "=f"(v.y), "=f"(v.z), "=f"(v.w) : "r"(a));
    return v;
}
__device__ __forceinline__ void ldsm4(uint32_t& r0, uint32_t& r1, uint32_t& r2, uint32_t& r3,
                                      uint32_t addr) {
    asm volatile("ldmatrix.sync.aligned.m8n8.x4.shared.b16 {%0,%1,%2,%3}, [%4];"
                 : "=r"(r0), "=r"(r1), "=r"(r2), "=r"(r3) : "r"(addr));
}
__device__ __forceinline__ void ldsm2(uint32_t& r0, uint32_t& r1, uint32_t addr) {
    asm volatile("ldmatrix.sync.aligned.m8n8.x2.shared.b16 {%0,%1}, [%2];"
                 : "=r"(r0), "=r"(r1) : "r"(addr));
}
__device__ __forceinline__ void mma_bf16(float* c, uint32_t a0, uint32_t a1, uint32_t a2,
                                         uint32_t a3, uint32_t b0, uint32_t b1) {
    asm volatile(
        "mma.sync.aligned.m16n8k16.row.col.f32.bf16.bf16.f32 "
        "{%0,%1,%2,%3}, {%4,%5,%6,%7}, {%8,%9}, {%0,%1,%2,%3};"
        : "+f"(c[0]), "+f"(c[1]), "+f"(c[2]), "+f"(c[3])
        : "r"(a0), "r"(a1), "r"(a2), "r"(a3), "r"(b0), "r"(b1));
}
__device__ __forceinline__ void cp_async16(uint32_t dst, const float* src) {
    asm volatile("cp.async.cg.shared.global [%0], [%1], 16;" :: "r"(dst), "l"(src));
}
#define CP_COMMIT() asm volatile("cp.async.commit_group;")
#define CP_WAIT0()  asm volatile("cp.async.wait_group 0;" ::: "memory")

#define REDW(v) { v += __shfl_xor_sync(0xffffffffu, v, 4);  \
                  v += __shfl_xor_sync(0xffffffffu, v, 8);  \
                  v += __shfl_xor_sync(0xffffffffu, v, 16); }

// Convert one float4 (cols 4f..4f+3 of row r) to bf16 hi/lo and store (row-major).
__device__ __forceinline__ void conv_store(float4 v, uint32_t hi_base, uint32_t lo_base,
                                           int r, int f, float& ssq) {
    ssq += v.x * v.x + v.y * v.y + v.z * v.z + v.w * v.w;
    uint32_t h0 = packbf(v.x, v.y);
    uint32_t h1 = packbf(v.z, v.w);
    float fx = __uint_as_float(h0 << 16), fy = __uint_as_float(h0 & 0xffff0000u);
    float fz = __uint_as_float(h1 << 16), fw = __uint_as_float(h1 & 0xffff0000u);
    uint32_t l0 = packbf(v.x - fx, v.y - fy);
    uint32_t l1 = packbf(v.z - fz, v.w - fw);
    uint32_t o = (uint32_t)r * STRB + (uint32_t)f * 8u;
    sts64(hi_base + o, h0, h1);
    sts64(lo_base + o, l0, l1);
}

// Async gather of one 64-row raw fp32 tile (4 threads per row).
// Thread (rt = tid>>2, p = tid&3) copies f = p, p+4, ... — the exact bytes the
// SAME thread later reads in the convert phase, so wait_group-0 + the loop-top
// barrier fully order the single-buffer reuse.
__device__ __forceinline__ void prefetch_raw(const int* __restrict__ toks,
                                             const float* __restrict__ emb,
                                             uint32_t rawbase, int tid)
{
    int rt = tid >> 2, p = tid & 3;
    long tok = toks[rt];
    const float* src = emb + tok * (long)E_SZ;
    uint32_t dst = rawbase + (uint32_t)rt * RSTR_B;
#pragma unroll
    for (int i = 0; i < 19; i++) {
        int f = p + 4 * i;
        if (f < 75) cp_async16(dst + (uint32_t)f * 16u, src + f * 4);
    }
}

__global__ void __launch_bounds__(NT, 1)
knrm_mma(const int* __restrict__ doctoks, const int* __restrict__ querytoks,
         const float* __restrict__ emb, const float* __restrict__ mus,
         const float* __restrict__ sigmas, const float* __restrict__ fcw,
         const float* __restrict__ fcb, float* __restrict__ out)
{
    extern __shared__ char smb[];
    const uint32_t sb = smem_u32(smb);
    float* rnd  = (float*)(smb + OFF_RND);
    float* rnq  = (float*)(smb + OFF_RNQ);
    float* red  = (float*)(smb + OFF_RED);
    float* qfin = (float*)(smb + OFF_QFIN);

    const int tid = threadIdx.x;
    const int b   = blockIdx.x;
    const int wid = tid >> 5, lane = tid & 31;
    const int* dtoks = doctoks + b * D_SZ;

    // Kick off async gather of tile 0 (overlaps query phase + init).
    prefetch_raw(dtoks, emb, sb + OFF_RAW, tid);
    CP_COMMIT();

    // Zero bf16 padding cols 300..311 (bytes 600..623) of all 160 bf16 rows.
    if (tid < 160) {
        uint32_t base;
        if (tid < 64)       base = sb + OFF_AHI + (uint32_t)tid * STRB;
        else if (tid < 128) base = sb + OFF_ALO + (uint32_t)(tid - 64) * STRB;
        else if (tid < 144) base = sb + OFF_BHI + (uint32_t)(tid - 128) * STRB;
        else                base = sb + OFF_BLO + (uint32_t)(tid - 144) * STRB;
        sts64(base + 600, 0u, 0u);
        sts64(base + 608, 0u, 0u);
        sts64(base + 616, 0u, 0u);
    }

    // ---- Query tile: convert to bf16 hi/lo + inverse norms ----
    {
        int q = tid >> 4, p = tid & 15;
        int tok = querytoks[b * Q_SZ + q];
        const float4* src = (const float4*)(emb + (long)tok * E_SZ);
        float ss = 0.f;
#pragma unroll
        for (int i = 0; i < 5; i++) {
            int f = p + 16 * i;
            if (f < 75)
                conv_store(src[f], sb + OFF_BHI, sb + OFF_BLO, q, f, ss);
        }
        ss += __shfl_xor_sync(0xffffffffu, ss, 1);
        ss += __shfl_xor_sync(0xffffffffu, ss, 2);
        ss += __shfl_xor_sync(0xffffffffu, ss, 4);
        ss += __shfl_xor_sync(0xffffffffu, ss, 8);
        if (p == 0) rnq[q] = 1.f / (sqrtf(ss) + 1e-9f);
    }
    __syncthreads();    // rnq visible before the cross-thread rq reads below (R14 bug fix)

    // RBF constants
    const float mu0   = mus[0];
    const float delta = mus[1] - mus[0];
    float sg = sigmas[0];
    const float c2a = -0.72134752044448169f / (sg * sg);
    const float mu10 = mus[10];
    sg = sigmas[10];
    const float c2b = -0.72134752044448169f / (sg * sg);

    // warp = rg*2 + nh: rg picks 16 doc rows, nh picks 8 q cols
    const int rg = wid >> 1;
    const int nh = wid & 1;
    const uint32_t lrow = lane & 15;
    const uint32_t lkof = (uint32_t)(lane >> 4) * 16u;
    const uint32_t aAH = sb + OFF_AHI + (16 * rg + lrow) * STRB + lkof;
    const uint32_t aAL = sb + OFF_ALO + (16 * rg + lrow) * STRB + lkof;
    const uint32_t brow = (uint32_t)(nh * 8) + (lane & 7);
    const uint32_t bkof = (uint32_t)((lane >> 3) & 1) * 16u;
    const uint32_t aBH = sb + OFF_BHI + brow * STRB + bkof;
    const uint32_t aBL = sb + OFF_BLO + brow * STRB + bkof;

    // sim coordinates
    const int m  = lane & 3;
    const int r0 = 16 * rg + (lane >> 2);
    const int r1 = r0 + 8;
    const int q0 = nh * 8 + 2 * m;
    const float rq0 = rnq[q0], rq1 = rnq[q0 + 1];

    float kq[2][K_SZ], ssim[2];
#pragma unroll
    for (int j = 0; j < 2; j++) {
        ssim[j] = 0.f;
#pragma unroll
        for (int k = 0; k < K_SZ; k++) kq[j][k] = 0.f;
    }

    for (int c = 0; c < NTILE; c++) {
        CP_WAIT0();                 // raw tile c resident (this thread's own gathers)
        __syncthreads();            // previous MMA done reading A; all converts may start

        // ---- convert raw fp32 -> bf16 hi/lo A + doc norms (4 threads/row) ----
        {
            int rt = tid >> 2, p = tid & 3;
            uint32_t rsrc = sb + OFF_RAW + (uint32_t)rt * RSTR_B;
            float ss = 0.f;
#pragma unroll
            for (int i = 0; i < 19; i++) {
                int f = p + 4 * i;
                if (f < 75) {
                    float4 v = lds128(rsrc + (uint32_t)f * 16u);
                    conv_store(v, sb + OFF_AHI, sb + OFF_ALO, rt, f, ss);
                }
            }
            ss += __shfl_xor_sync(0xffffffffu, ss, 1);
            ss += __shfl_xor_sync(0xffffffffu, ss, 2);
            if (p == 0) rnd[rt] = 1.f / (sqrtf(ss) + 1e-9f);
        }
        __syncthreads();            // A + rnd ready; raw fully consumed by all threads

        // gather next tile -> overlaps MMA + RBF below
        if (c + 1 < NTILE) {
            prefetch_raw(dtoks + (c + 1) * MT, emb, sb + OFF_RAW, tid);
            CP_COMMIT();
        }

        // ---- MMA: 19 k-steps, 3 split-passes ----
        float accH[4] = {0.f, 0.f, 0.f, 0.f};
        float accM[4] = {0.f, 0.f, 0.f, 0.f};
        float accL[4] = {0.f, 0.f, 0.f, 0.f};
#pragma unroll
        for (int ks = 0; ks < NKS; ks++) {
            uint32_t ko = (uint32_t)ks * 32u;
            uint32_t ah0, ah1, ah2, ah3, al0, al1, al2, al3;
            uint32_t bh0, bh1, bl0, bl1;
            ldsm4(ah0, ah1, ah2, ah3, aAH + ko);
            ldsm4(al0, al1, al2, al3, aAL + ko);
            ldsm2(bh0, bh1, aBH + ko);
            ldsm2(bl0, bl1, aBL + ko);
            mma_bf16(accH, ah0, ah1, ah2, ah3, bh0, bh1);
            mma_bf16(accM, ah0, ah1, ah2, ah3, bl0, bl1);
            mma_bf16(accL, al0, al1, al2, al3, bh0, bh1);
        }

        // ---- normalize + RBF (sims in registers) ----
        float rd0 = rnd[r0], rd1 = rnd[r1];
        float sv[4];
        sv[0] = (accH[0] + accM[0] + accL[0]) * rd0 * rq0;
        sv[1] = (accH[1] + accM[1] + accL[1]) * rd0 * rq1;
        sv[2] = (accH[2] + accM[2] + accL[2]) * rd1 * rq0;
        sv[3] = (accH[3] + accM[3] + accL[3]) * rd1 * rq1;
#pragma unroll
        for (int i = 0; i < 4; i++) {
            int j = i & 1;
            float s = sv[i];
            ssim[j] += s;
            float tt = s - mu0;
#pragma unroll
            for (int k = 0; k < 10; k++) {
                kq[j][k] += ex2f(c2a * tt * tt);
                tt -= delta;
            }
            tt = s - mu10;
            kq[j][10] += ex2f(c2b * tt * tt);
        }
        // no sync needed here: next iteration's top barrier orders conv writes after this MMA/RBF
    }

    // ---- reduce: in-warp over row bits, cross-warp over rg via smem ----
#pragma unroll
    for (int j = 0; j < 2; j++) {
        REDW(ssim[j]);
#pragma unroll
        for (int k = 0; k < K_SZ; k++) REDW(kq[j][k]);
    }
    if (lane < 4) {
        float* r = red + wid * 96 + lane * 24;   // lane == m
#pragma unroll
        for (int j = 0; j < 2; j++) {
#pragma unroll
            for (int k = 0; k < K_SZ; k++) r[j * 12 + k] = kq[j][k];
            r[j * 12 + 11] = ssim[j];
        }
    }
    __syncthreads();
    if (tid < Q_SZ * 12) {
        int q = tid / 12, v = tid - q * 12;
        int nhq = q >> 3, mq = (q & 7) >> 1, j = q & 1;
        float sum = 0.f;
#pragma unroll
        for (int rgi = 0; rgi < 4; rgi++)
            sum += red[(2 * rgi + nhq) * 96 + mq * 24 + j * 12 + v];
        qfin[q * 12 + v] = sum;
    }
    __syncthreads();

    // ---- log, mask, Q-sum, FC head ----
    float partial = 0.f;
    if (tid < K_SZ) {
        float acc2 = 0.f;
        for (int q = 0; q < Q_SZ; q++)
            if (qfin[q * 12 + 11] != 0.0f)
                acc2 += logf(qfin[q * 12 + tid] + 1e-6f);
        partial = acc2 * fcw[tid];
    }
    if (tid < 32) {
#pragma unroll
        for (int mm = 16; mm; mm >>= 1)
            partial += __shfl_xor_sync(0xffffffffu, partial, mm);
        if (tid == 0) out[b] = partial + fcb[0];
    }
}

extern "C" void kernel_launch(void* const* d_in, const int* in_sizes, int n_in,
                              void* d_out, int out_size)
{
    const int*   doctoks   = (const int*)d_in[0];
    const int*   querytoks = (const int*)d_in[1];
    // d_in[2] = query_idf (unused by the reference)
    const float* emb       = (const float*)d_in[3];
    const float* mus       = (const float*)d_in[4];
    const float* sigmas    = (const float*)d_in[5];
    const float* fc_w      = (const float*)d_in[6];
    const float* fc_b      = (const float*)d_in[7];
    float* out = (float*)d_out;

    cudaFuncSetAttribute(knrm_mma, cudaFuncAttributeMaxDynamicSharedMemorySize, SMEM_BYTES);
    knrm_mma<<<B_SZ, NT, SMEM_BYTES>>>(doctoks, querytoks, emb, mus, sigmas,
                                       fc_w, fc_b, out);
}

// round 16
// speedup vs baseline: 1.1805x; 1.1805x over previous
#include <cuda_runtime.h>
#include <cstdint>

// KNRM: mma.sync bf16 3-split; next tile's raw fp32 prefetched into REGISTERS
// during MMA/RBF; convert phase is pure ALU/STS. B=128, Q=16, D=1024, E=300, K=11.
#define B_SZ 128
#define Q_SZ 16
#define D_SZ 1024
#define E_SZ 300
#define K_SZ 11
#define NT 256
#define MT 64                    // doc rows per tile
#define NTILE 16
#define NKS 19                   // k-steps of 16 (covers 304 >= 300)
#define STRB 624                 // bf16 row stride bytes (312 cols)

#define OFF_AHI  0                           // 64 x 624 = 39936
#define OFF_ALO  39936                       // 64 x 624
#define OFF_BHI  79872                       // 16 x 624
#define OFF_BLO  89856                       // 16 x 624
#define OFF_RND  99840                       // 64 floats
#define OFF_RNQ  100096                      // 16 floats
#define OFF_RED  100160                      // 8 warps x 4 m x 24 floats = 3072 B
#define OFF_QFIN 103232                      // 192 floats
#define SMEM_BYTES 104016

__device__ __forceinline__ uint32_t smem_u32(const void* p) {
    uint32_t a;
    asm("{ .reg .u64 t; cvta.to.shared.u64 t, %1; cvt.u32.u64 %0, t; }" : "=r"(a) : "l"(p));
    return a;
}
__device__ __forceinline__ float ex2f(float x) {
    float y; asm("ex2.approx.f32 %0, %1;" : "=f"(y) : "f"(x)); return y;
}
__device__ __forceinline__ uint32_t packbf(float lo, float hi) {
    uint32_t r;
    asm("cvt.rn.bf16x2.f32 %0, %1, %2;" : "=r"(r) : "f"(hi), "f"(lo));
    return r;
}
__device__ __forceinline__ void sts64(uint32_t a, uint32_t x, uint32_t y) {
    asm volatile("st.shared.v2.b32 [%0], {%1, %2};" :: "r"(a), "r"(x), "r"(y) : "memory");
}
__device__ __forceinline__ void ldsm4(uint32_t& r0, uint32_t& r1, uint32_t& r2, uint32_t& r3,
                                      uint32_t addr) {
    asm volatile("ldmatrix.sync.aligned.m8n8.x4.shared.b16 {%0,%1,%2,%3}, [%4];"
                 : "=r"(r0), "=r"(r1), "=r"(r2), "=r"(r3) : "r"(addr));
}
__device__ __forceinline__ void ldsm2(uint32_t& r0, uint32_t& r1, uint32_t addr) {
    asm volatile("ldmatrix.sync.aligned.m8n8.x2.shared.b16 {%0,%1}, [%2];"
                 : "=r"(r0), "=r"(r1) : "r"(addr));
}
__device__ __forceinline__ void mma_bf16(float* c, uint32_t a0, uint32_t a1, uint32_t a2,
                                         uint32_t a3, uint32_t b0, uint32_t b1) {
    asm volatile(
        "mma.sync.aligned.m16n8k16.row.col.f32.bf16.bf16.f32 "
        "{%0,%1,%2,%3}, {%4,%5,%6,%7}, {%8,%9}, {%0,%1,%2,%3};"
        : "+f"(c[0]), "+f"(c[1]), "+f"(c[2]), "+f"(c[3])
        : "r"(a0), "r"(a1), "r"(a2), "r"(a3), "r"(b0), "r"(b1));
}

#define REDW(v) { v += __shfl_xor_sync(0xffffffffu, v, 4);  \
                  v += __shfl_xor_sync(0xffffffffu, v, 8);  \
                  v += __shfl_xor_sync(0xffffffffu, v, 16); }

// Convert one float4 (cols 4f..4f+3 of row r) to bf16 hi/lo and store (row-major).
__device__ __forceinline__ void conv_store(float4 v, uint32_t hi_base, uint32_t lo_base,
                                           int r, int f, float& ssq) {
    ssq += v.x * v.x + v.y * v.y + v.z * v.z + v.w * v.w;
    uint32_t h0 = packbf(v.x, v.y);
    uint32_t h1 = packbf(v.z, v.w);
    float fx = __uint_as_float(h0 << 16), fy = __uint_as_float(h0 & 0xffff0000u);
    float fz = __uint_as_float(h1 << 16), fw = __uint_as_float(h1 & 0xffff0000u);
    uint32_t l0 = packbf(v.x - fx, v.y - fy);
    uint32_t l1 = packbf(v.z - fz, v.w - fw);
    uint32_t o = (uint32_t)r * STRB + (uint32_t)f * 8u;
    sts64(hi_base + o, h0, h1);
    sts64(lo_base + o, l0, l1);
}

// Load this thread's quarter-row of one 64-row tile into registers.
// rt = tid>>2 (row), p = tid&3: f = p, p+4, ..., guarded at f<75.
__device__ __forceinline__ void load_raw(float4* vreg, const int* __restrict__ toks,
                                         const float* __restrict__ emb, int rt, int p)
{
    long tok = toks[rt];
    const float4* src = (const float4*)(emb + tok * (long)E_SZ);
#pragma unroll
    for (int i = 0; i < 19; i++) {
        int f = p + 4 * i;
        if (f < 75) vreg[i] = __ldg(src + f);
        else        vreg[i] = make_float4(0.f, 0.f, 0.f, 0.f);
    }
}

__global__ void __launch_bounds__(NT, 1)
knrm_mma(const int* __restrict__ doctoks, const int* __restrict__ querytoks,
         const float* __restrict__ emb, const float* __restrict__ mus,
         const float* __restrict__ sigmas, const float* __restrict__ fcw,
         const float* __restrict__ fcb, float* __restrict__ out)
{
    extern __shared__ char smb[];
    const uint32_t sb = smem_u32(smb);
    float* rnd  = (float*)(smb + OFF_RND);
    float* rnq  = (float*)(smb + OFF_RNQ);
    float* red  = (float*)(smb + OFF_RED);
    float* qfin = (float*)(smb + OFF_QFIN);

    const int tid = threadIdx.x;
    const int b   = blockIdx.x;
    const int wid = tid >> 5, lane = tid & 31;
    const int* dtoks = doctoks + b * D_SZ;
    const int rt = tid >> 2, pq = tid & 3;

    // Prefetch tile 0 into registers (latency overlaps query phase + init).
    float4 vreg[19];
    load_raw(vreg, dtoks, emb, rt, pq);

    // Zero bf16 padding cols 300..311 (bytes 600..623) of all 160 bf16 rows.
    if (tid < 160) {
        uint32_t base;
        if (tid < 64)       base = sb + OFF_AHI + (uint32_t)tid * STRB;
        else if (tid < 128) base = sb + OFF_ALO + (uint32_t)(tid - 64) * STRB;
        else if (tid < 144) base = sb + OFF_BHI + (uint32_t)(tid - 128) * STRB;
        else                base = sb + OFF_BLO + (uint32_t)(tid - 144) * STRB;
        sts64(base + 600, 0u, 0u);
        sts64(base + 608, 0u, 0u);
        sts64(base + 616, 0u, 0u);
    }

    // ---- Query tile: convert to bf16 hi/lo + inverse norms ----
    {
        int q = tid >> 4, p = tid & 15;
        int tok = querytoks[b * Q_SZ + q];
        const float4* src = (const float4*)(emb + (long)tok * E_SZ);
        float ss = 0.f;
#pragma unroll
        for (int i = 0; i < 5; i++) {
            int f = p + 16 * i;
            if (f < 75)
                conv_store(src[f], sb + OFF_BHI, sb + OFF_BLO, q, f, ss);
        }
        ss += __shfl_xor_sync(0xffffffffu, ss, 1);
        ss += __shfl_xor_sync(0xffffffffu, ss, 2);
        ss += __shfl_xor_sync(0xffffffffu, ss, 4);
        ss += __shfl_xor_sync(0xffffffffu, ss, 8);
        if (p == 0) rnq[q] = 1.f / (sqrtf(ss) + 1e-9f);
    }
    __syncthreads();    // rnq + B visible before the cross-thread rq reads below

    // RBF constants
    const float mu0   = mus[0];
    const float delta = mus[1] - mus[0];
    float sg = sigmas[0];
    const float c2a = -0.72134752044448169f / (sg * sg);
    const float mu10 = mus[10];
    sg = sigmas[10];
    const float c2b = -0.72134752044448169f / (sg * sg);

    // warp = rg*2 + nh: rg picks 16 doc rows, nh picks 8 q cols
    const int rg = wid >> 1;
    const int nh = wid & 1;
    const uint32_t lrow = lane & 15;
    const uint32_t lkof = (uint32_t)(lane >> 4) * 16u;
    const uint32_t aAH = sb + OFF_AHI + (16 * rg + lrow) * STRB + lkof;
    const uint32_t aAL = sb + OFF_ALO + (16 * rg + lrow) * STRB + lkof;
    const uint32_t brow = (uint32_t)(nh * 8) + (lane & 7);
    const uint32_t bkof = (uint32_t)((lane >> 3) & 1) * 16u;
    const uint32_t aBH = sb + OFF_BHI + brow * STRB + bkof;
    const uint32_t aBL = sb + OFF_BLO + brow * STRB + bkof;

    // sim coordinates
    const int m  = lane & 3;
    const int r0 = 16 * rg + (lane >> 2);
    const int r1 = r0 + 8;
    const int q0 = nh * 8 + 2 * m;
    const float rq0 = rnq[q0], rq1 = rnq[q0 + 1];

    float kq[2][K_SZ], ssim[2];
#pragma unroll
    for (int j = 0; j < 2; j++) {
        ssim[j] = 0.f;
#pragma unroll
        for (int k = 0; k < K_SZ; k++) kq[j][k] = 0.f;
    }

    for (int c = 0; c < NTILE; c++) {
        // previous iteration's MMA has finished reading A (barrier below at end
        // of the convert phase serves both directions across iterations)

        // ---- convert vreg -> bf16 hi/lo A + doc norms (pure ALU/STS) ----
        {
            float ss = 0.f;
#pragma unroll
            for (int i = 0; i < 19; i++) {
                int f = pq + 4 * i;
                if (f < 75)
                    conv_store(vreg[i], sb + OFF_AHI, sb + OFF_ALO, rt, f, ss);
            }
            ss += __shfl_xor_sync(0xffffffffu, ss, 1);
            ss += __shfl_xor_sync(0xffffffffu, ss, 2);
            if (pq == 0) rnd[rt] = 1.f / (sqrtf(ss) + 1e-9f);
        }
        __syncthreads();            // A + rnd ready for all warps

        // ---- prefetch tile c+1 into registers; latency covered by MMA+RBF ----
        if (c + 1 < NTILE)
            load_raw(vreg, dtoks + (c + 1) * MT, emb, rt, pq);

        // ---- MMA: 19 k-steps, 3 split-passes ----
        float accH[4] = {0.f, 0.f, 0.f, 0.f};
        float accM[4] = {0.f, 0.f, 0.f, 0.f};
        float accL[4] = {0.f, 0.f, 0.f, 0.f};
#pragma unroll
        for (int ks = 0; ks < NKS; ks++) {
            uint32_t ko = (uint32_t)ks * 32u;
            uint32_t ah0, ah1, ah2, ah3, al0, al1, al2, al3;
            uint32_t bh0, bh1, bl0, bl1;
            ldsm4(ah0, ah1, ah2, ah3, aAH + ko);
            ldsm4(al0, al1, al2, al3, aAL + ko);
            ldsm2(bh0, bh1, aBH + ko);
            ldsm2(bl0, bl1, aBL + ko);
            mma_bf16(accH, ah0, ah1, ah2, ah3, bh0, bh1);
            mma_bf16(accM, ah0, ah1, ah2, ah3, bl0, bl1);
            mma_bf16(accL, al0, al1, al2, al3, bh0, bh1);
        }

        // ---- normalize + RBF (sims in registers) ----
        float rd0 = rnd[r0], rd1 = rnd[r1];
        float sv[4];
        sv[0] = (accH[0] + accM[0] + accL[0]) * rd0 * rq0;
        sv[1] = (accH[1] + accM[1] + accL[1]) * rd0 * rq1;
        sv[2] = (accH[2] + accM[2] + accL[2]) * rd1 * rq0;
        sv[3] = (accH[3] + accM[3] + accL[3]) * rd1 * rq1;
#pragma unroll
        for (int i = 0; i < 4; i++) {
            int j = i & 1;
            float s = sv[i];
            ssim[j] += s;
            float tt = s - mu0;
#pragma unroll
            for (int k = 0; k < 10; k++) {
                kq[j][k] += ex2f(c2a * tt * tt);
                tt -= delta;
            }
            tt = s - mu10;
            kq[j][10] += ex2f(c2b * tt * tt);
        }
        __syncthreads();            // all warps done reading A before next convert
    }

    // ---- reduce: in-warp over row bits, cross-warp over rg via smem ----
#pragma unroll
    for (int j = 0; j < 2; j++) {
        REDW(ssim[j]);
#pragma unroll
        for (int k = 0; k < K_SZ; k++) REDW(kq[j][k]);
    }
    if (lane < 4) {
        float* r = red + wid * 96 + lane * 24;   // lane == m
#pragma unroll
        for (int j = 0; j < 2; j++) {
#pragma unroll
            for (int k = 0; k < K_SZ; k++) r[j * 12 + k] = kq[j][k];
            r[j * 12 + 11] = ssim[j];
        }
    }
    __syncthreads();
    if (tid < Q_SZ * 12) {
        int q = tid / 12, v = tid - q * 12;
        int nhq = q >> 3, mq = (q & 7) >> 1, j = q & 1;
        float sum = 0.f;
#pragma unroll
        for (int rgi = 0; rgi < 4; rgi++)
            sum += red[(2 * rgi + nhq) * 96 + mq * 24 + j * 12 + v];
        qfin[q * 12 + v] = sum;
    }
    __syncthreads();

    // ---- log, mask, Q-sum, FC head ----
    float partial = 0.f;
    if (tid < K_SZ) {
        float acc2 = 0.f;
        for (int q = 0; q < Q_SZ; q++)
            if (qfin[q * 12 + 11] != 0.0f)
                acc2 += logf(qfin[q * 12 + tid] + 1e-6f);
        partial = acc2 * fcw[tid];
    }
    if (tid < 32) {
#pragma unroll
        for (int mm = 16; mm; mm >>= 1)
            partial += __shfl_xor_sync(0xffffffffu, partial, mm);
        if (tid == 0) out[b] = partial + fcb[0];
    }
}

extern "C" void kernel_launch(void* const* d_in, const int* in_sizes, int n_in,
                              void* d_out, int out_size)
{
    const int*   doctoks   = (const int*)d_in[0];
    const int*   querytoks = (const int*)d_in[1];
    // d_in[2] = query_idf (unused by the reference)
    const float* emb       = (const float*)d_in[3];
    const float* mus       = (const float*)d_in[4];
    const float* sigmas    = (const float*)d_in[5];
    const float* fc_w      = (const float*)d_in[6];
    const float* fc_b      = (const float*)d_in[7];
    float* out = (float*)d_out;

    cudaFuncSetAttribute(knrm_mma, cudaFuncAttributeMaxDynamicSharedMemorySize, SMEM_BYTES);
    knrm_mma<<<B_SZ, NT, SMEM_BYTES>>>(doctoks, querytoks, emb, mus, sigmas,
                                       fc_w, fc_b, out);
}